// round 1
// baseline (speedup 1.0000x reference)
#include <cuda_runtime.h>
#include <stdint.h>

#define BB 4
#define NP 8192
#define NG 8192
#define T  256        // threads per block
#define Q  4          // queries per thread
#define GS 16         // gt slices (acc kernel)
#define PS 16         // pred slices (com kernel)
#define PSL (NP / PS) // 512 pred points per slice

#define INF_BITS 0x7F800000u

// ---------------- device scratch (no allocs allowed) ----------------
__device__ float    g_gt[BB][3][NG];   // compacted valid gt, SoA, sentinel-filled
__device__ int      g_gtidx[BB][NG];   // original gt index of compacted entry
__device__ int      g_cnt[BB];
__device__ unsigned g_prmin[BB * NP];  // per-pred min d2 (float bits)
__device__ unsigned g_gtmin[BB * NG];  // per-ORIGINAL-gt min d2 (float bits)
__device__ int      g_fmt;             // 1 = gt_valid is int32, 0 = 1-byte bool

// ---------------- packed f32x2 helpers ----------------
__device__ __forceinline__ unsigned long long f2pk(float lo, float hi) {
    unsigned long long r;
    asm("mov.b64 %0, {%1,%2};" : "=l"(r) : "f"(lo), "f"(hi));
    return r;
}
__device__ __forceinline__ unsigned long long add2(unsigned long long a, unsigned long long b) {
    unsigned long long r;
    asm("add.rn.f32x2 %0, %1, %2;" : "=l"(r) : "l"(a), "l"(b));
    return r;
}
__device__ __forceinline__ unsigned long long mul2(unsigned long long a, unsigned long long b) {
    unsigned long long r;
    asm("mul.rn.f32x2 %0, %1, %2;" : "=l"(r) : "l"(a), "l"(b));
    return r;
}
__device__ __forceinline__ unsigned long long fma2(unsigned long long a, unsigned long long b,
                                                   unsigned long long c) {
    unsigned long long r;
    asm("fma.rn.f32x2 %0, %1, %2, %3;" : "=l"(r) : "l"(a), "l"(b), "l"(c));
    return r;
}
__device__ __forceinline__ void upk(unsigned long long v, float& lo, float& hi) {
    asm("mov.b64 {%0,%1}, %2;" : "=f"(lo), "=f"(hi) : "l"(v));
}

// Scan a (negated) smem tile of len points (len % 4 == 0) against Q packed
// queries, maintaining two running mins per query.
__device__ __forceinline__ void scan_tile(
    const float* __restrict__ sx, const float* __restrict__ sy, const float* __restrict__ sz,
    int len,
    const unsigned long long qx[Q], const unsigned long long qy[Q], const unsigned long long qz[Q],
    float m0[Q], float m1[Q])
{
    for (int j = 0; j < len; j += 4) {
        float4 vx = *reinterpret_cast<const float4*>(sx + j);
        float4 vy = *reinterpret_cast<const float4*>(sy + j);
        float4 vz = *reinterpret_cast<const float4*>(sz + j);
        unsigned long long gx0 = f2pk(vx.x, vx.y), gx1 = f2pk(vx.z, vx.w);
        unsigned long long gy0 = f2pk(vy.x, vy.y), gy1 = f2pk(vy.z, vy.w);
        unsigned long long gz0 = f2pk(vz.x, vz.y), gz1 = f2pk(vz.z, vz.w);
#pragma unroll
        for (int q = 0; q < Q; q++) {
            {
                unsigned long long dx = add2(qx[q], gx0);
                unsigned long long dy = add2(qy[q], gy0);
                unsigned long long dz = add2(qz[q], gz0);
                unsigned long long d  = fma2(dz, dz, fma2(dy, dy, mul2(dx, dx)));
                float dl, dh; upk(d, dl, dh);
                m0[q] = fminf(m0[q], dl);
                m1[q] = fminf(m1[q], dh);
            }
            {
                unsigned long long dx = add2(qx[q], gx1);
                unsigned long long dy = add2(qy[q], gy1);
                unsigned long long dz = add2(qz[q], gz1);
                unsigned long long d  = fma2(dz, dz, fma2(dy, dy, mul2(dx, dx)));
                float dl, dh; upk(d, dl, dh);
                m0[q] = fminf(m0[q], dl);
                m1[q] = fminf(m1[q], dh);
            }
        }
    }
}

// ---------------- kernels ----------------
__global__ void k_init() {
    int stride = gridDim.x * blockDim.x;
    int i = blockIdx.x * blockDim.x + threadIdx.x;
    float* gtf = &g_gt[0][0][0];
    for (int k = i; k < BB * 3 * NG; k += stride) gtf[k] = 1e18f;  // sentinel
    for (int k = i; k < BB * NP; k += stride) g_prmin[k] = INF_BITS;
    for (int k = i; k < BB * NG; k += stride) g_gtmin[k] = INF_BITS;
    if (i < BB) g_cnt[i] = 0;
    if (i == 0) g_fmt = 1;
}

// gt_valid may be 1-byte bool (numpy/jax bool) or int32. If any 32-bit word
// of the first 8192 words (safe under both layouts) exceeds 1, it's byte-bool.
__global__ void k_detect(const unsigned* __restrict__ w) {
    int i = blockIdx.x * blockDim.x + threadIdx.x;
    if (i < (BB * NG) / 4) {
        if (w[i] > 1u) g_fmt = 0;
    }
}

__global__ void k_compact(const float* __restrict__ gt, const void* __restrict__ valid) {
    int i = blockIdx.x * blockDim.x + threadIdx.x;
    if (i >= BB * NG) return;
    int b = i / NG, g = i % NG;
    bool v;
    if (g_fmt)
        v = (reinterpret_cast<const int*>(valid)[i] != 0);
    else
        v = (reinterpret_cast<const unsigned char*>(valid)[i] != 0);
    if (v) {
        int p = atomicAdd(&g_cnt[b], 1);
        const float* s = gt + (size_t)i * 3;
        g_gt[b][0][p] = s[0];
        g_gt[b][1][p] = s[1];
        g_gt[b][2][p] = s[2];
        g_gtidx[b][p] = g;
    }
}

// accuracy: per pred point, min d2 over valid gt (sliced over blockIdx.y)
__global__ void __launch_bounds__(T) k_acc(const float* __restrict__ pr) {
    int b = blockIdx.z;
    int cnt = g_cnt[b];
    int npad = (cnt + 3) & ~3;
    int L = (((npad + GS - 1) / GS) + 3) & ~3;  // slice length, mult of 4, <= 512
    int s0 = blockIdx.y * L;
    int s1 = min(s0 + L, npad);
    if (s0 >= s1) return;

    __shared__ __align__(16) float sx[NG / GS], sy[NG / GS], sz[NG / GS];
    for (int i = threadIdx.x; i < s1 - s0; i += T) {
        sx[i] = -g_gt[b][0][s0 + i];
        sy[i] = -g_gt[b][1][s0 + i];
        sz[i] = -g_gt[b][2][s0 + i];
    }
    __syncthreads();

    int qbase = blockIdx.x * (T * Q);
    unsigned long long qx[Q], qy[Q], qz[Q];
    float m0[Q], m1[Q];
    int qi[Q];
#pragma unroll
    for (int q = 0; q < Q; q++) {
        int qq = qbase + threadIdx.x + q * T;
        qi[q] = qq;
        const float* p = pr + ((size_t)b * NP + qq) * 3;
        float x = p[0], y = p[1], z = p[2];
        qx[q] = f2pk(x, x); qy[q] = f2pk(y, y); qz[q] = f2pk(z, z);
        m0[q] = __uint_as_float(INF_BITS);
        m1[q] = __uint_as_float(INF_BITS);
    }

    scan_tile(sx, sy, sz, s1 - s0, qx, qy, qz, m0, m1);

#pragma unroll
    for (int q = 0; q < Q; q++) {
        float m = fminf(m0[q], m1[q]);
        atomicMin(&g_prmin[b * NP + qi[q]], __float_as_uint(m));
    }
}

// completeness: per valid gt point, min d2 over ALL pred (sliced over blockIdx.y)
__global__ void __launch_bounds__(T) k_com(const float* __restrict__ pr) {
    int b = blockIdx.z;
    int cnt = g_cnt[b];
    int qbase = blockIdx.x * (T * Q);
    if (qbase >= cnt) return;  // whole block beyond valid count

    __shared__ __align__(16) float sx[PSL], sy[PSL], sz[PSL];
    int s0 = blockIdx.y * PSL;
    for (int i = threadIdx.x; i < PSL; i += T) {
        const float* p = pr + ((size_t)b * NP + s0 + i) * 3;
        sx[i] = -p[0];
        sy[i] = -p[1];
        sz[i] = -p[2];
    }
    __syncthreads();

    unsigned long long qx[Q], qy[Q], qz[Q];
    float m0[Q], m1[Q];
    int qi[Q];
#pragma unroll
    for (int q = 0; q < Q; q++) {
        int qq = qbase + threadIdx.x + q * T;
        qi[q] = qq;
        // beyond-cnt queries read sentinel coords (1e18): harmless, result discarded
        float x = g_gt[b][0][qq], y = g_gt[b][1][qq], z = g_gt[b][2][qq];
        qx[q] = f2pk(x, x); qy[q] = f2pk(y, y); qz[q] = f2pk(z, z);
        m0[q] = __uint_as_float(INF_BITS);
        m1[q] = __uint_as_float(INF_BITS);
    }

    scan_tile(sx, sy, sz, PSL, qx, qy, qz, m0, m1);

#pragma unroll
    for (int q = 0; q < Q; q++) {
        if (qi[q] < cnt) {
            float m = fminf(m0[q], m1[q]);
            int orig = g_gtidx[b][qi[q]];
            atomicMin(&g_gtmin[b * NG + orig], __float_as_uint(m));
        }
    }
}

__global__ void k_final(float* __restrict__ out) {
    __shared__ float sa;
    __shared__ float sc[BB];
    if (threadIdx.x == 0) sa = 0.f;
    if (threadIdx.x < BB) sc[threadIdx.x] = 0.f;
    __syncthreads();

    float la = 0.f;
    for (int i = threadIdx.x; i < BB * NP; i += blockDim.x)
        la += __uint_as_float(g_prmin[i]);
    atomicAdd(&sa, la);

    for (int b = 0; b < BB; b++) {
        float lc = 0.f;
        for (int i = threadIdx.x; i < NG; i += blockDim.x) {
            unsigned v = g_gtmin[b * NG + i];
            if (v != INF_BITS) lc += __uint_as_float(v);  // only valid gt were written
        }
        atomicAdd(&sc[b], lc);
    }
    __syncthreads();

    if (threadIdx.x == 0) {
        float loss_acc = sa / (float)(BB * NP);
        float loss_com = 0.f;
        for (int b = 0; b < BB; b++)
            loss_com += sc[b] / fmaxf((float)g_cnt[b], 1.f);
        loss_com /= (float)BB;
        out[0] = 2.f * (loss_acc + loss_com);  // acc + com + cd, cd = acc + com
    }
}

// ---------------- launch ----------------
extern "C" void kernel_launch(void* const* d_in, const int* in_sizes, int n_in,
                              void* d_out, int out_size) {
    const float* pr    = (const float*)d_in[0];  // [B,NP,3] f32
    const float* gt    = (const float*)d_in[1];  // [B,NG,3] f32
    const void*  valid = d_in[2];                // [B,NG] bool(1B) or int32

    k_init<<<256, 256>>>();
    k_detect<<<(BB * NG / 4 + 255) / 256, 256>>>((const unsigned*)valid);
    k_compact<<<(BB * NG + 255) / 256, 256>>>(gt, valid);
    k_acc<<<dim3(NP / (T * Q), GS, BB), T>>>(pr);
    k_com<<<dim3(NG / (T * Q), PS, BB), T>>>(pr);
    k_final<<<1, 256>>>((float*)d_out);
}

// round 2
// speedup vs baseline: 1.2774x; 1.2774x over previous
#include <cuda_runtime.h>
#include <stdint.h>

#define BB 4
#define NP 8192
#define NG 8192
#define T  256        // threads per block
#define Q  4          // queries per thread
#define GS 16         // gt slices (acc direction)
#define PS 16         // pred slices (com direction)
#define PSL (NP / PS) // 512 pred points per slice

#define INF_BITS 0x7F800000u

// ---------------- device scratch (no allocs allowed) ----------------
__device__ float    g_gt[BB][3][NG];   // compacted valid gt, SoA (sentinel coords = 0)
__device__ float    g_gtsq[BB][NG];    // |g|^2 per compacted gt (sentinel = +inf)
__device__ int      g_gtidx[BB][NG];   // original gt index of compacted entry
__device__ int      g_cnt[BB];
__device__ unsigned g_prmin[BB * NP];  // per-pred min d2 (float bits)
__device__ unsigned g_gtmin[BB * NG];  // per-ORIGINAL-gt min d2 (float bits)
__device__ int      g_fmt;             // 1 = gt_valid int32, 0 = 1-byte bool

// ---------------- packed f32x2 helpers ----------------
__device__ __forceinline__ unsigned long long f2pk(float lo, float hi) {
    unsigned long long r;
    asm("mov.b64 %0, {%1,%2};" : "=l"(r) : "f"(lo), "f"(hi));
    return r;
}
__device__ __forceinline__ unsigned long long fma2(unsigned long long a, unsigned long long b,
                                                   unsigned long long c) {
    unsigned long long r;
    asm("fma.rn.f32x2 %0, %1, %2, %3;" : "=l"(r) : "l"(a), "l"(b), "l"(c));
    return r;
}
__device__ __forceinline__ void upk(unsigned long long v, float& lo, float& hi) {
    asm("mov.b64 {%0,%1}, %2;" : "=f"(lo), "=f"(hi) : "l"(v));
}

// ---------------- kernels ----------------
__global__ void k_init() {
    int stride = gridDim.x * blockDim.x;
    int i = blockIdx.x * blockDim.x + threadIdx.x;
    float* gtf = &g_gt[0][0][0];
    for (int k = i; k < BB * 3 * NG; k += stride) gtf[k] = 0.f;           // sentinel coords
    float* sqf = &g_gtsq[0][0];
    for (int k = i; k < BB * NG; k += stride) sqf[k] = __int_as_float(INF_BITS);
    for (int k = i; k < BB * NP; k += stride) g_prmin[k] = INF_BITS;
    for (int k = i; k < BB * NG; k += stride) g_gtmin[k] = INF_BITS;
    if (i < BB) g_cnt[i] = 0;
    if (i == 0) g_fmt = 1;
}

// gt_valid may be 1-byte bool or int32; any 32-bit word > 1 => byte-bool.
__global__ void k_detect(const unsigned* __restrict__ w) {
    int i = blockIdx.x * blockDim.x + threadIdx.x;
    if (i < (BB * NG) / 4) {
        if (w[i] > 1u) g_fmt = 0;
    }
}

__global__ void k_compact(const float* __restrict__ gt, const void* __restrict__ valid) {
    int i = blockIdx.x * blockDim.x + threadIdx.x;
    if (i >= BB * NG) return;
    int b = i / NG, g = i % NG;
    bool v;
    if (g_fmt)
        v = (reinterpret_cast<const int*>(valid)[i] != 0);
    else
        v = (reinterpret_cast<const unsigned char*>(valid)[i] != 0);
    if (v) {
        int p = atomicAdd(&g_cnt[b], 1);
        const float* s = gt + (size_t)i * 3;
        float x = s[0], y = s[1], z = s[2];
        g_gt[b][0][p] = x;
        g_gt[b][1][p] = y;
        g_gt[b][2][p] = z;
        g_gtsq[b][p]  = x * x + y * y + z * z;
        g_gtidx[b][p] = g;
    }
}

// Fused bidirectional Chamfer kernel.
// blockIdx.z in [0, 2*BB): z < BB -> accuracy direction (queries = pred, tile = gt)
//                          z >= BB -> completeness (queries = compacted gt, tile = pred)
// Tile stored pair-SoA: s[2k] = (x0,x1,y0,y1), s[2k+1] = (z0,z1,sq0,sq1).
// Per 2 tile points, per query: t = fma2(-2qx, gx, fma2(-2qy, gy, fma2(-2qz, gz, gsq)))
// min tracked on each packed half; final result = min + |q|^2 (clamped at 0).
__global__ void __launch_bounds__(T) k_cd(const float* __restrict__ pr) {
    int zz = blockIdx.z;
    int b = zz & (BB - 1);
    bool is_acc = zz < BB;
    int cnt = g_cnt[b];

    __shared__ __align__(16) float4 s[PSL];  // up to 512 points (8 KB)

    int tileLen, t0;
    if (is_acc) {
        int npad = (cnt + 7) & ~7;
        int L = (((npad + GS - 1) / GS) + 7) & ~7;   // slice len, mult of 8
        t0 = blockIdx.y * L;
        int t1 = min(t0 + L, npad);
        if (t0 >= t1) return;
        tileLen = t1 - t0;
        for (int i = threadIdx.x; i < tileLen; i += T) {
            float x = g_gt[b][0][t0 + i];
            float y = g_gt[b][1][t0 + i];
            float z = g_gt[b][2][t0 + i];
            float sq = g_gtsq[b][t0 + i];
            float* base = reinterpret_cast<float*>(&s[(i >> 1) * 2]);
            int h = i & 1;
            base[0 + h] = x; base[2 + h] = y; base[4 + h] = z; base[6 + h] = sq;
        }
    } else {
        if (blockIdx.x * (T * Q) >= cnt) return;   // whole block beyond valid count
        t0 = blockIdx.y * PSL;
        tileLen = PSL;
        for (int i = threadIdx.x; i < tileLen; i += T) {
            const float* p = pr + ((size_t)b * NP + t0 + i) * 3;
            float x = p[0], y = p[1], z = p[2];
            float sq = x * x + y * y + z * z;
            float* base = reinterpret_cast<float*>(&s[(i >> 1) * 2]);
            int h = i & 1;
            base[0 + h] = x; base[2 + h] = y; base[4 + h] = z; base[6 + h] = sq;
        }
    }
    __syncthreads();

    int qbase = blockIdx.x * (T * Q);
    unsigned long long q2x[Q], q2y[Q], q2z[Q];
    float qsq[Q], m0[Q], m1[Q];
    int qi[Q];
#pragma unroll
    for (int q = 0; q < Q; q++) {
        int qq = qbase + threadIdx.x + q * T;
        qi[q] = qq;
        float x, y, z, sq;
        if (is_acc) {
            const float* p = pr + ((size_t)b * NP + qq) * 3;
            x = p[0]; y = p[1]; z = p[2];
            sq = x * x + y * y + z * z;
        } else {
            x = g_gt[b][0][qq]; y = g_gt[b][1][qq]; z = g_gt[b][2][qq];
            sq = 0.f;  // result discarded for qq >= cnt; valid qq uses real sq below
            if (qq < cnt) sq = g_gtsq[b][qq];
        }
        float nx = -2.f * x, ny = -2.f * y, nz = -2.f * z;
        q2x[q] = f2pk(nx, nx); q2y[q] = f2pk(ny, ny); q2z[q] = f2pk(nz, nz);
        qsq[q] = sq;
        m0[q] = __uint_as_float(INF_BITS);
        m1[q] = __uint_as_float(INF_BITS);
    }

    int pairs = tileLen >> 1;
#pragma unroll 4
    for (int k = 0; k < pairs; k++) {
        float4 a  = s[k * 2];
        float4 bv = s[k * 2 + 1];
        unsigned long long gx = f2pk(a.x, a.y);
        unsigned long long gy = f2pk(a.z, a.w);
        unsigned long long gz = f2pk(bv.x, bv.y);
        unsigned long long gs = f2pk(bv.z, bv.w);
#pragma unroll
        for (int q = 0; q < Q; q++) {
            unsigned long long t = fma2(q2x[q], gx, fma2(q2y[q], gy, fma2(q2z[q], gz, gs)));
            float tl, th; upk(t, tl, th);
            m0[q] = fminf(m0[q], tl);
            m1[q] = fminf(m1[q], th);
        }
    }

#pragma unroll
    for (int q = 0; q < Q; q++) {
        float m = fmaxf(fminf(m0[q], m1[q]) + qsq[q], 0.f);
        if (is_acc) {
            atomicMin(&g_prmin[b * NP + qi[q]], __float_as_uint(m));
        } else if (qi[q] < cnt) {
            int orig = g_gtidx[b][qi[q]];
            atomicMin(&g_gtmin[b * NG + orig], __float_as_uint(m));
        }
    }
}

__global__ void k_final(float* __restrict__ out) {
    __shared__ float sa;
    __shared__ float sc[BB];
    if (threadIdx.x == 0) sa = 0.f;
    if (threadIdx.x < BB) sc[threadIdx.x] = 0.f;
    __syncthreads();

    float la = 0.f;
    for (int i = threadIdx.x; i < BB * NP; i += blockDim.x)
        la += __uint_as_float(g_prmin[i]);
    atomicAdd(&sa, la);

    for (int b = 0; b < BB; b++) {
        float lc = 0.f;
        for (int i = threadIdx.x; i < NG; i += blockDim.x) {
            unsigned v = g_gtmin[b * NG + i];
            if (v != INF_BITS) lc += __uint_as_float(v);  // only valid gt were written
        }
        atomicAdd(&sc[b], lc);
    }
    __syncthreads();

    if (threadIdx.x == 0) {
        float loss_acc = sa / (float)(BB * NP);
        float loss_com = 0.f;
        for (int b = 0; b < BB; b++)
            loss_com += sc[b] / fmaxf((float)g_cnt[b], 1.f);
        loss_com /= (float)BB;
        out[0] = 2.f * (loss_acc + loss_com);  // acc + com + cd, cd = acc + com
    }
}

// ---------------- launch ----------------
extern "C" void kernel_launch(void* const* d_in, const int* in_sizes, int n_in,
                              void* d_out, int out_size) {
    const float* pr    = (const float*)d_in[0];  // [B,NP,3] f32
    const float* gt    = (const float*)d_in[1];  // [B,NG,3] f32
    const void*  valid = d_in[2];                // [B,NG] bool(1B) or int32

    k_init<<<256, 256>>>();
    k_detect<<<(BB * NG / 4 + 255) / 256, 256>>>((const unsigned*)valid);
    k_compact<<<(BB * NG + 255) / 256, 256>>>(gt, valid);
    k_cd<<<dim3(NP / (T * Q), GS, 2 * BB), T>>>(pr);
    k_final<<<1, 256>>>((float*)d_out);
}